// round 1
// baseline (speedup 1.0000x reference)
#include <cuda_runtime.h>
#include <math.h>

#define N_NODES 50000
#define N_EDGES 600000

// ---------------- scratch (device globals; no allocation allowed) -----------
__device__ int      g_deg[N_NODES];
__device__ int      g_cnt2[N_NODES];
__device__ int      g_off[N_NODES + 1];
__device__ int      g_pos[N_NODES];
__device__ unsigned g_csr[N_EDGES];                 // src | (mask<<31)
__device__ float    g_agg[(size_t)N_NODES * 256];   // conv1 uses stride 128, conv2 stride 256
__device__ float    g_h  [(size_t)N_NODES * 256];
__device__ float    g_h2 [(size_t)N_NODES * 256];

// ---------------- CSR build --------------------------------------------------
__global__ void zero_kernel() {
    int i = blockIdx.x * blockDim.x + threadIdx.x;
    if (i < N_NODES) { g_deg[i] = 0; g_cnt2[i] = 0; }
}

__global__ void count_kernel(const int* __restrict__ dst, const unsigned* __restrict__ mask) {
    int e = blockIdx.x * blockDim.x + threadIdx.x;
    if (e >= N_EDGES) return;
    int d = dst[e];
    atomicAdd(&g_deg[d], 1);
    if (mask[e] != 0u) atomicAdd(&g_cnt2[d], 1);
}

__global__ void scan_kernel() {
    __shared__ int sh[1024];
    __shared__ int s_run;
    int tx = threadIdx.x;
    if (tx == 0) s_run = 0;
    __syncthreads();
    for (int base = 0; base < N_NODES; base += 1024) {
        int i = base + tx;
        int v = (i < N_NODES) ? g_deg[i] : 0;
        sh[tx] = v;
        __syncthreads();
        for (int o = 1; o < 1024; o <<= 1) {
            int t = (tx >= o) ? sh[tx - o] : 0;
            __syncthreads();
            sh[tx] += t;
            __syncthreads();
        }
        int run  = s_run;
        int excl = run + sh[tx] - v;
        if (i < N_NODES) { g_off[i] = excl; g_pos[i] = excl; }
        __syncthreads();
        if (tx == 0) s_run = run + sh[1023];
        __syncthreads();
    }
    if (tx == 0) g_off[N_NODES] = s_run;
}

__global__ void scatter_kernel(const int* __restrict__ src, const int* __restrict__ dst,
                               const unsigned* __restrict__ mask) {
    int e = blockIdx.x * blockDim.x + threadIdx.x;
    if (e >= N_EDGES) return;
    int d = dst[e];
    int slot = atomicAdd(&g_pos[d], 1);
    unsigned ent = (unsigned)src[e];
    if (mask[e] != 0u) ent |= 0x80000000u;
    g_csr[slot] = ent;
}

// ---------------- aggregation (warp per node, gather) ------------------------
__global__ void agg1_kernel(const float* __restrict__ x) {
    int w    = (blockIdx.x * blockDim.x + threadIdx.x) >> 5;
    int lane = threadIdx.x & 31;
    if (w >= N_NODES) return;
    int beg = g_off[w], end = g_off[w + 1];
    float4 acc = make_float4(0.f, 0.f, 0.f, 0.f);
    for (int p = beg; p < end; ++p) {
        unsigned ent = g_csr[p];
        int s = (int)(ent & 0x7fffffffu);
        float4 t = ((const float4*)(x + (size_t)s * 128))[lane];
        acc.x += t.x; acc.y += t.y; acc.z += t.z; acc.w += t.w;
    }
    int deg = end - beg;
    float inv = 1.0f / (float)(deg > 1 ? deg : 1);
    acc.x *= inv; acc.y *= inv; acc.z *= inv; acc.w *= inv;
    ((float4*)(g_agg + (size_t)w * 128))[lane] = acc;
}

__global__ void agg2_kernel() {
    int w    = (blockIdx.x * blockDim.x + threadIdx.x) >> 5;
    int lane = threadIdx.x & 31;
    if (w >= N_NODES) return;
    int beg = g_off[w], end = g_off[w + 1];
    float4 a0 = make_float4(0.f, 0.f, 0.f, 0.f);
    float4 a1 = make_float4(0.f, 0.f, 0.f, 0.f);
    for (int p = beg; p < end; ++p) {
        unsigned ent = g_csr[p];
        if (ent & 0x80000000u) {
            int s = (int)(ent & 0x7fffffffu);
            const float4* hr = (const float4*)(g_h + (size_t)s * 256);
            float4 t0 = hr[lane];
            float4 t1 = hr[lane + 32];
            a0.x += t0.x; a0.y += t0.y; a0.z += t0.z; a0.w += t0.w;
            a1.x += t1.x; a1.y += t1.y; a1.z += t1.z; a1.w += t1.w;
        }
    }
    int c = g_cnt2[w];
    float inv = 1.0f / (float)(c > 1 ? c : 1);
    a0.x *= inv; a0.y *= inv; a0.z *= inv; a0.w *= inv;
    a1.x *= inv; a1.y *= inv; a1.z *= inv; a1.w *= inv;
    float4* outr = (float4*)(g_agg + (size_t)w * 256);
    outr[lane]      = a0;
    outr[lane + 32] = a1;
}

// ---------------- fused SAGE layer GEMM --------------------------------------
// H[r,c] computed for full 256-wide row per block so L2-norm is warp-local.
// y1 = A1@Wl^T + A2@Wr^T + bl ; SKIP: y2 = A2@Ws^T + bs
// out = tanh(y1/max(||y1||,eps) [+ y2])
template <bool SKIP>
__global__ __launch_bounds__(256, 2) void layer_kernel(
    const float* __restrict__ A1, const float* __restrict__ A2, int K,
    const float* __restrict__ Wl, const float* __restrict__ Wr, const float* __restrict__ bl,
    const float* __restrict__ Wsk, const float* __restrict__ bsk,
    float* __restrict__ H)
{
    extern __shared__ float sm[];
    float* sA1 = sm;                       // 32*33
    float* sA2 = sA1 + 32 * 33;            // 32*33
    float* sWl = sA2 + 32 * 33;            // 32*257
    float* sWr = sWl + 32 * 257;           // 32*257
    float* sWs = sWr + 32 * 257;           // 32*257 (only if SKIP)

    int tx   = threadIdx.x;
    int lane = tx & 31;
    int rg   = tx >> 5;
    int row0 = blockIdx.x * 32;

    float acc1[4][8];
    float acc2[4][8];
#pragma unroll
    for (int i = 0; i < 4; i++)
#pragma unroll
        for (int j = 0; j < 8; j++) { acc1[i][j] = 0.f; if (SKIP) acc2[i][j] = 0.f; }

    for (int k0 = 0; k0 < K; k0 += 32) {
#pragma unroll
        for (int i = 0; i < 4; i++) {
            int r  = i * 8 + rg;
            int gr = row0 + r;
            float v1 = 0.f, v2 = 0.f;
            if (gr < N_NODES) {
                v1 = A1[(size_t)gr * K + k0 + lane];
                v2 = A2[(size_t)gr * K + k0 + lane];
            }
            sA1[r * 33 + lane] = v1;
            sA2[r * 33 + lane] = v2;
        }
#pragma unroll
        for (int i = 0; i < 32; i++) {
            int c = rg + 8 * i;
            sWl[lane * 257 + c] = Wl[(size_t)c * K + k0 + lane];
            sWr[lane * 257 + c] = Wr[(size_t)c * K + k0 + lane];
            if (SKIP) sWs[lane * 257 + c] = Wsk[(size_t)c * K + k0 + lane];
        }
        __syncthreads();
#pragma unroll
        for (int k = 0; k < 32; k++) {
            float a1[4], a2[4];
#pragma unroll
            for (int i = 0; i < 4; i++) {
                a1[i] = sA1[(rg * 4 + i) * 33 + k];
                a2[i] = sA2[(rg * 4 + i) * 33 + k];
            }
            float wl[8], wr[8], ws[8];
#pragma unroll
            for (int j = 0; j < 8; j++) {
                wl[j] = sWl[k * 257 + lane + 32 * j];
                wr[j] = sWr[k * 257 + lane + 32 * j];
                if (SKIP) ws[j] = sWs[k * 257 + lane + 32 * j];
            }
#pragma unroll
            for (int i = 0; i < 4; i++)
#pragma unroll
                for (int j = 0; j < 8; j++) {
                    acc1[i][j] = fmaf(a1[i], wl[j], acc1[i][j]);
                    acc1[i][j] = fmaf(a2[i], wr[j], acc1[i][j]);
                    if (SKIP) acc2[i][j] = fmaf(a2[i], ws[j], acc2[i][j]);
                }
        }
        __syncthreads();
    }

    float blv[8], bsv[8];
#pragma unroll
    for (int j = 0; j < 8; j++) {
        blv[j] = bl[lane + 32 * j];
        if (SKIP) bsv[j] = bsk[lane + 32 * j];
    }
#pragma unroll
    for (int i = 0; i < 4; i++)
#pragma unroll
        for (int j = 0; j < 8; j++) acc1[i][j] += blv[j];

#pragma unroll
    for (int i = 0; i < 4; i++) {
        float s = 0.f;
#pragma unroll
        for (int j = 0; j < 8; j++) s += acc1[i][j] * acc1[i][j];
#pragma unroll
        for (int o = 16; o; o >>= 1) s += __shfl_xor_sync(0xffffffffu, s, o);
        int gr = row0 + rg * 4 + i;
        if (gr < N_NODES) {
            float inv = 1.0f / fmaxf(sqrtf(s), 1e-12f);
#pragma unroll
            for (int j = 0; j < 8; j++) {
                float v = acc1[i][j] * inv;
                if (SKIP) v += acc2[i][j] + bsv[j];
                v = tanhf(v);
                H[(size_t)gr * 256 + lane + 32 * j] = v;
            }
        }
    }
}

// ---------------- final projection: out = H2 @ Wo^T + bo ---------------------
__global__ __launch_bounds__(256, 2) void out_kernel(
    const float* __restrict__ A, const float* __restrict__ Wo,
    const float* __restrict__ bo, float* __restrict__ O)
{
    __shared__ float sA[32 * 33];
    __shared__ float sW[32 * 129];
    int tx   = threadIdx.x;
    int lane = tx & 31;
    int rg   = tx >> 5;
    int row0 = blockIdx.x * 32;

    float acc[4][4];
#pragma unroll
    for (int i = 0; i < 4; i++)
#pragma unroll
        for (int j = 0; j < 4; j++) acc[i][j] = 0.f;

    for (int k0 = 0; k0 < 256; k0 += 32) {
#pragma unroll
        for (int i = 0; i < 4; i++) {
            int r  = i * 8 + rg;
            int gr = row0 + r;
            sA[r * 33 + lane] = (gr < N_NODES) ? A[(size_t)gr * 256 + k0 + lane] : 0.f;
        }
#pragma unroll
        for (int i = 0; i < 16; i++) {
            int c = rg + 8 * i;     // c in [0,128)
            sW[lane * 129 + c] = Wo[(size_t)c * 256 + k0 + lane];
        }
        __syncthreads();
#pragma unroll
        for (int k = 0; k < 32; k++) {
            float a[4], w[4];
#pragma unroll
            for (int i = 0; i < 4; i++) a[i] = sA[(rg * 4 + i) * 33 + k];
#pragma unroll
            for (int j = 0; j < 4; j++) w[j] = sW[k * 129 + lane + 32 * j];
#pragma unroll
            for (int i = 0; i < 4; i++)
#pragma unroll
                for (int j = 0; j < 4; j++) acc[i][j] = fmaf(a[i], w[j], acc[i][j]);
        }
        __syncthreads();
    }
    float bov[4];
#pragma unroll
    for (int j = 0; j < 4; j++) bov[j] = bo[lane + 32 * j];
#pragma unroll
    for (int i = 0; i < 4; i++) {
        int gr = row0 + rg * 4 + i;
        if (gr < N_NODES) {
#pragma unroll
            for (int j = 0; j < 4; j++)
                O[(size_t)gr * 128 + lane + 32 * j] = acc[i][j] + bov[j];
        }
    }
}

// ---------------- launch ------------------------------------------------------
extern "C" void kernel_launch(void* const* d_in, const int* in_sizes, int n_in,
                              void* d_out, int out_size)
{
    (void)in_sizes; (void)n_in; (void)out_size;
    const float*    x    = (const float*)d_in[0];
    const int*      ei   = (const int*)d_in[1];
    const unsigned* mask = (const unsigned*)d_in[2];   // nonzero test: works for i32 and f32 encodings
    const float*    W1l  = (const float*)d_in[3];
    const float*    b1   = (const float*)d_in[4];
    const float*    W1r  = (const float*)d_in[5];
    const float*    Ws   = (const float*)d_in[6];
    const float*    bs   = (const float*)d_in[7];
    const float*    W2l  = (const float*)d_in[8];
    const float*    b2   = (const float*)d_in[9];
    const float*    W2r  = (const float*)d_in[10];
    const float*    Wo   = (const float*)d_in[11];
    const float*    bo   = (const float*)d_in[12];
    float*          out  = (float*)d_out;

    const int* src = ei;
    const int* dst = ei + N_EDGES;

    void *p_agg, *p_h, *p_h2;
    cudaGetSymbolAddress(&p_agg, g_agg);
    cudaGetSymbolAddress(&p_h,   g_h);
    cudaGetSymbolAddress(&p_h2,  g_h2);
    float* agg = (float*)p_agg;
    float* h   = (float*)p_h;
    float* h2  = (float*)p_h2;

    size_t smem_skip   = (size_t)(2 * 32 * 33 + 3 * 32 * 257) * sizeof(float); // 107136 B
    size_t smem_noskip = (size_t)(2 * 32 * 33 + 2 * 32 * 257) * sizeof(float); //  74240 B
    cudaFuncSetAttribute(layer_kernel<true>,  cudaFuncAttributeMaxDynamicSharedMemorySize, (int)smem_skip);
    cudaFuncSetAttribute(layer_kernel<false>, cudaFuncAttributeMaxDynamicSharedMemorySize, (int)smem_noskip);

    int nb_nodes = (N_NODES + 255) / 256;
    int nb_edges = (N_EDGES + 255) / 256;
    int nb_warps = (N_NODES * 32 + 255) / 256;
    int nb_rows  = (N_NODES + 31) / 32;

    // CSR build
    zero_kernel<<<nb_nodes, 256>>>();
    count_kernel<<<nb_edges, 256>>>(dst, mask);
    scan_kernel<<<1, 1024>>>();
    scatter_kernel<<<nb_edges, 256>>>(src, dst, mask);

    // Layer 1: agg (mean over ALL edges), then fused GEMM+norm+skip+tanh
    agg1_kernel<<<nb_warps, 256>>>(x);
    layer_kernel<true><<<nb_rows, 256, smem_skip>>>(
        agg, x, 128, W1l, W1r, b1, Ws, bs, h);

    // Layer 2: agg (mean over masked edges), fused GEMM+norm+tanh
    agg2_kernel<<<nb_warps, 256>>>();
    layer_kernel<false><<<nb_rows, 256, smem_noskip>>>(
        agg, h, 256, W2l, W2r, b2, nullptr, nullptr, h2);

    // Output projection
    out_kernel<<<nb_rows, 256>>>(h2, Wo, bo, out);
}

// round 3
// speedup vs baseline: 3.1722x; 3.1722x over previous
#include <cuda_runtime.h>
#include <math.h>
#include <stdint.h>

#define N_NODES 50000
#define N_EDGES 600000

// ---------------- scratch (device globals; no allocation allowed) -----------
__device__ int      g_deg[N_NODES];
__device__ int      g_cnt2[N_NODES];
__device__ int      g_off[N_NODES + 1];
__device__ int      g_pos[N_NODES];
__device__ int      g_bsum[128];
__device__ int      g_boff[128];
__device__ unsigned g_csr[N_EDGES];                 // src | (mask<<31)
__device__ float    g_agg[(size_t)N_NODES * 256];
__device__ float    g_h  [(size_t)N_NODES * 256];
__device__ float    g_h2 [(size_t)N_NODES * 256];

// ======================= mma.sync tf32 helpers (sm_80+ PTX; no 103a-only ops) =
__device__ __forceinline__ unsigned f2tf32(float x) {
    unsigned u; asm("cvt.rna.tf32.f32 %0, %1;" : "=r"(u) : "f"(x)); return u;
}

// D(16x8) += A(16x8,row) * B(8x8,col)   tf32 inputs, f32 accum
__device__ __forceinline__ void mma8(float* d, const unsigned* a, const unsigned* b) {
    asm volatile(
        "mma.sync.aligned.m16n8k8.row.col.f32.tf32.tf32.f32 "
        "{%0,%1,%2,%3}, {%4,%5,%6,%7}, {%8,%9}, {%0,%1,%2,%3};"
        : "+f"(d[0]), "+f"(d[1]), "+f"(d[2]), "+f"(d[3])
        : "r"(a[0]), "r"(a[1]), "r"(a[2]), "r"(a[3]), "r"(b[0]), "r"(b[1]));
}

// Load ROWS x 32 fp32 tile into smem (row stride 36 floats), tf32-rounded.
template <int ROWS>
__device__ __forceinline__ void load_tile(float* s, const float* __restrict__ g,
                                          int ld, int k0, int row0, int maxrow) {
    int tid = threadIdx.x;
#pragma unroll
    for (int it = 0; it < ROWS * 8 / 256; ++it) {
        int idx = it * 256 + tid;
        int r = idx >> 3, c4 = idx & 7;
        float4 v = make_float4(0.f, 0.f, 0.f, 0.f);
        if (row0 + r < maxrow) v = *(const float4*)(g + (size_t)(row0 + r) * ld + k0 + c4 * 4);
        uint4 u;
        u.x = f2tf32(v.x); u.y = f2tf32(v.y); u.z = f2tf32(v.z); u.w = f2tf32(v.w);
        *(uint4*)(s + r * 36 + c4 * 4) = u;
    }
}

// ---------------- CSR build --------------------------------------------------
__global__ void zero_kernel() {
    int i = blockIdx.x * blockDim.x + threadIdx.x;
    if (i < N_NODES) { g_deg[i] = 0; g_cnt2[i] = 0; }
}

__global__ void count_kernel(const int* __restrict__ dst, const unsigned* __restrict__ mask) {
    int e = blockIdx.x * blockDim.x + threadIdx.x;
    if (e >= N_EDGES) return;
    int d = dst[e];
    atomicAdd(&g_deg[d], 1);
    if (mask[e] != 0u) atomicAdd(&g_cnt2[d], 1);
}

__global__ void scan1_kernel() {
    __shared__ int sh[512];
    int b = blockIdx.x, tid = threadIdx.x;
    int i = b * 512 + tid;
    int v = (i < N_NODES) ? g_deg[i] : 0;
    sh[tid] = v;
    __syncthreads();
    for (int o = 1; o < 512; o <<= 1) {
        int t = (tid >= o) ? sh[tid - o] : 0;
        __syncthreads();
        sh[tid] += t;
        __syncthreads();
    }
    if (i < N_NODES) g_off[i] = sh[tid] - v;
    if (tid == 511) g_bsum[b] = sh[511];
}

__global__ void scan2_kernel() {
    __shared__ int sh[128];
    int tid = threadIdx.x;
    const int nb = (N_NODES + 511) / 512;
    int v = (tid < nb) ? g_bsum[tid] : 0;
    sh[tid] = v;
    __syncthreads();
    for (int o = 1; o < 128; o <<= 1) {
        int t = (tid >= o) ? sh[tid - o] : 0;
        __syncthreads();
        sh[tid] += t;
        __syncthreads();
    }
    if (tid < nb) g_boff[tid] = sh[tid] - v;
}

__global__ void scan3_kernel() {
    int i = blockIdx.x * blockDim.x + threadIdx.x;
    if (i < N_NODES) {
        int o = g_off[i] + g_boff[i >> 9];
        g_off[i] = o;
        g_pos[i] = o;
        if (i == 0) g_off[N_NODES] = N_EDGES;
    }
}

__global__ void scatter_kernel(const int* __restrict__ src, const int* __restrict__ dst,
                               const unsigned* __restrict__ mask) {
    int e = blockIdx.x * blockDim.x + threadIdx.x;
    if (e >= N_EDGES) return;
    int d = dst[e];
    int slot = atomicAdd(&g_pos[d], 1);
    unsigned ent = (unsigned)src[e];
    if (mask[e] != 0u) ent |= 0x80000000u;
    g_csr[slot] = ent;
}

// ---------------- aggregation (warp per node, gather) ------------------------
__global__ void agg1_kernel(const float* __restrict__ x) {
    int w    = (blockIdx.x * blockDim.x + threadIdx.x) >> 5;
    int lane = threadIdx.x & 31;
    if (w >= N_NODES) return;
    int beg = g_off[w], end = g_off[w + 1];
    float4 acc = make_float4(0.f, 0.f, 0.f, 0.f);
    for (int p = beg; p < end; ++p) {
        unsigned ent = g_csr[p];
        int s = (int)(ent & 0x7fffffffu);
        float4 t = ((const float4*)(x + (size_t)s * 128))[lane];
        acc.x += t.x; acc.y += t.y; acc.z += t.z; acc.w += t.w;
    }
    int deg = end - beg;
    float inv = 1.0f / (float)(deg > 1 ? deg : 1);
    acc.x *= inv; acc.y *= inv; acc.z *= inv; acc.w *= inv;
    ((float4*)(g_agg + (size_t)w * 128))[lane] = acc;
}

__global__ void agg2_kernel() {
    int w    = (blockIdx.x * blockDim.x + threadIdx.x) >> 5;
    int lane = threadIdx.x & 31;
    if (w >= N_NODES) return;
    int beg = g_off[w], end = g_off[w + 1];
    float4 a0 = make_float4(0.f, 0.f, 0.f, 0.f);
    float4 a1 = make_float4(0.f, 0.f, 0.f, 0.f);
    for (int p = beg; p < end; ++p) {
        unsigned ent = g_csr[p];
        if (ent & 0x80000000u) {
            int s = (int)(ent & 0x7fffffffu);
            const float4* hr = (const float4*)(g_h + (size_t)s * 256);
            float4 t0 = hr[lane];
            float4 t1 = hr[lane + 32];
            a0.x += t0.x; a0.y += t0.y; a0.z += t0.z; a0.w += t0.w;
            a1.x += t1.x; a1.y += t1.y; a1.z += t1.z; a1.w += t1.w;
        }
    }
    int c = g_cnt2[w];
    float inv = 1.0f / (float)(c > 1 ? c : 1);
    a0.x *= inv; a0.y *= inv; a0.z *= inv; a0.w *= inv;
    a1.x *= inv; a1.y *= inv; a1.z *= inv; a1.w *= inv;
    float4* outr = (float4*)(g_agg + (size_t)w * 256);
    outr[lane]      = a0;
    outr[lane + 32] = a1;
}

// ---------------- fused SAGE layer via mma.sync tf32 --------------------------
// Per CTA: 64 rows x 256 cols. 8 warps: warp (wm,wn) = rows 16*wm..+15, cols 128*wn..+127.
// acc1 = A1@Wl^T + A2@Wr^T (+bl, L2-normalized); SKIP: acc2 = A2@Ws^T (+bs added post-norm).
template <bool SKIP>
__global__ __launch_bounds__(256, 1) void layer_mma(
    const float* __restrict__ A1, const float* __restrict__ A2, int K,
    const float* __restrict__ Wl, const float* __restrict__ Wr,
    const float* __restrict__ bl,
    const float* __restrict__ Wsk, const float* __restrict__ bsk,
    float* __restrict__ H)
{
    extern __shared__ float sm[];
    float* sBL  = sm;            // 256
    float* sBS  = sm + 256;      // 256
    float* sred = sm + 512;      // 128
    float* sA1  = sm + 1024;     // 64*36 = 2304
    float* sA2  = sA1 + 2304;
    float* sWl  = sA2 + 2304;    // 256*36 = 9216
    float* sWr  = sWl + 9216;
    float* sWs  = sWr + 9216;

    int tid = threadIdx.x, lane = tid & 31, w = tid >> 5;
    int wm = w >> 1, wn = w & 1;
    int g = lane >> 2, t = lane & 3;
    int row0 = blockIdx.x * 64;

    if (tid < 256) {
        sBL[tid] = bl[tid];
        if (SKIP) sBS[tid] = bsk[tid];
    }

    float acc1[16][4];
    float acc2[16][4];
#pragma unroll
    for (int nt = 0; nt < 16; nt++)
#pragma unroll
        for (int j = 0; j < 4; j++) { acc1[nt][j] = 0.f; if (SKIP) acc2[nt][j] = 0.f; }

    for (int c = 0; c < (K >> 5); c++) {
        int k0 = c << 5;
        load_tile<64>(sA1, A1, K, k0, row0, N_NODES);
        load_tile<64>(sA2, A2, K, k0, row0, N_NODES);
        load_tile<256>(sWl, Wl, K, k0, 0, 256);
        load_tile<256>(sWr, Wr, K, k0, 0, 256);
        if (SKIP) load_tile<256>(sWs, Wsk, K, k0, 0, 256);
        __syncthreads();
#pragma unroll
        for (int ks = 0; ks < 4; ks++) {
            int kb = ks * 8;
            unsigned a1f[4], a2f[4];
            const float* pa1 = sA1 + (16 * wm + g) * 36 + kb + t;
            const float* pa2 = sA2 + (16 * wm + g) * 36 + kb + t;
            a1f[0] = __float_as_uint(pa1[0]);
            a1f[1] = __float_as_uint(pa1[8 * 36]);
            a1f[2] = __float_as_uint(pa1[4]);
            a1f[3] = __float_as_uint(pa1[8 * 36 + 4]);
            a2f[0] = __float_as_uint(pa2[0]);
            a2f[1] = __float_as_uint(pa2[8 * 36]);
            a2f[2] = __float_as_uint(pa2[4]);
            a2f[3] = __float_as_uint(pa2[8 * 36 + 4]);
#pragma unroll
            for (int nt = 0; nt < 16; nt++) {
                int n0 = 128 * wn + 8 * nt;
                const float* pw = sWl + (n0 + g) * 36 + kb + t;
                unsigned bf[2];
                bf[0] = __float_as_uint(pw[0]); bf[1] = __float_as_uint(pw[4]);
                mma8(acc1[nt], a1f, bf);
                pw = sWr + (n0 + g) * 36 + kb + t;
                bf[0] = __float_as_uint(pw[0]); bf[1] = __float_as_uint(pw[4]);
                mma8(acc1[nt], a2f, bf);
                if (SKIP) {
                    pw = sWs + (n0 + g) * 36 + kb + t;
                    bf[0] = __float_as_uint(pw[0]); bf[1] = __float_as_uint(pw[4]);
                    mma8(acc2[nt], a2f, bf);
                }
            }
        }
        __syncthreads();
    }

    // bias + per-row sum of squares
    float ssq0 = 0.f, ssq1 = 0.f;
#pragma unroll
    for (int nt = 0; nt < 16; nt++) {
        int col = 128 * wn + 8 * nt + 2 * t;
        acc1[nt][0] += sBL[col];
        acc1[nt][1] += sBL[col + 1];
        acc1[nt][2] += sBL[col];
        acc1[nt][3] += sBL[col + 1];
        ssq0 += acc1[nt][0] * acc1[nt][0] + acc1[nt][1] * acc1[nt][1];
        ssq1 += acc1[nt][2] * acc1[nt][2] + acc1[nt][3] * acc1[nt][3];
    }
    ssq0 += __shfl_xor_sync(0xffffffffu, ssq0, 1);
    ssq0 += __shfl_xor_sync(0xffffffffu, ssq0, 2);
    ssq1 += __shfl_xor_sync(0xffffffffu, ssq1, 1);
    ssq1 += __shfl_xor_sync(0xffffffffu, ssq1, 2);
    int r0 = 16 * wm + g, r1 = r0 + 8;
    if (t == 0) {
        sred[r0 * 2 + wn] = ssq0;
        sred[r1 * 2 + wn] = ssq1;
    }
    __syncthreads();
    float inv0 = 1.f / fmaxf(sqrtf(sred[r0 * 2] + sred[r0 * 2 + 1]), 1e-12f);
    float inv1 = 1.f / fmaxf(sqrtf(sred[r1 * 2] + sred[r1 * 2 + 1]), 1e-12f);
    int gr0 = row0 + r0, gr1 = row0 + r1;

#pragma unroll
    for (int nt = 0; nt < 16; nt++) {
        int col = 128 * wn + 8 * nt + 2 * t;
        float v0 = acc1[nt][0] * inv0, v1 = acc1[nt][1] * inv0;
        float v2 = acc1[nt][2] * inv1, v3 = acc1[nt][3] * inv1;
        if (SKIP) {
            v0 += acc2[nt][0] + sBS[col];
            v1 += acc2[nt][1] + sBS[col + 1];
            v2 += acc2[nt][2] + sBS[col];
            v3 += acc2[nt][3] + sBS[col + 1];
        }
        v0 = tanhf(v0); v1 = tanhf(v1); v2 = tanhf(v2); v3 = tanhf(v3);
        if (gr0 < N_NODES) *(float2*)(H + (size_t)gr0 * 256 + col) = make_float2(v0, v1);
        if (gr1 < N_NODES) *(float2*)(H + (size_t)gr1 * 256 + col) = make_float2(v2, v3);
    }
}

// ---------------- output projection via mma.sync tf32 -------------------------
// Per CTA: 64 rows x 128 cols. Warp (wm,wn): rows 16*wm, cols 64*wn (8 n-tiles).
__global__ __launch_bounds__(256, 1) void out_mma(
    const float* __restrict__ A, const float* __restrict__ Wo,
    const float* __restrict__ bo, float* __restrict__ O)
{
    extern __shared__ float sm[];
    float* sBO = sm;            // 128, pad to 256
    float* sA  = sm + 256;      // 64*36 = 2304
    float* sW  = sA + 2304;     // 128*36 = 4608

    int tid = threadIdx.x, lane = tid & 31, w = tid >> 5;
    int wm = w >> 1, wn = w & 1;
    int g = lane >> 2, t = lane & 3;
    int row0 = blockIdx.x * 64;

    if (tid < 128) sBO[tid] = bo[tid];

    float acc[8][4];
#pragma unroll
    for (int nt = 0; nt < 8; nt++)
#pragma unroll
        for (int j = 0; j < 4; j++) acc[nt][j] = 0.f;

    const int K = 256;
    for (int c = 0; c < 8; c++) {
        int k0 = c << 5;
        load_tile<64>(sA, A, K, k0, row0, N_NODES);
        load_tile<128>(sW, Wo, K, k0, 0, 128);
        __syncthreads();
#pragma unroll
        for (int ks = 0; ks < 4; ks++) {
            int kb = ks * 8;
            unsigned af[4];
            const float* pa = sA + (16 * wm + g) * 36 + kb + t;
            af[0] = __float_as_uint(pa[0]);
            af[1] = __float_as_uint(pa[8 * 36]);
            af[2] = __float_as_uint(pa[4]);
            af[3] = __float_as_uint(pa[8 * 36 + 4]);
#pragma unroll
            for (int nt = 0; nt < 8; nt++) {
                int n0 = 64 * wn + 8 * nt;
                const float* pw = sW + (n0 + g) * 36 + kb + t;
                unsigned bf[2];
                bf[0] = __float_as_uint(pw[0]); bf[1] = __float_as_uint(pw[4]);
                mma8(acc[nt], af, bf);
            }
        }
        __syncthreads();
    }

    int r0 = 16 * wm + g;
    int gr0 = row0 + r0, gr1 = gr0 + 8;
#pragma unroll
    for (int nt = 0; nt < 8; nt++) {
        int col = 64 * wn + 8 * nt + 2 * t;
        float b0 = sBO[col], b1 = sBO[col + 1];
        if (gr0 < N_NODES)
            *(float2*)(O + (size_t)gr0 * 128 + col) = make_float2(acc[nt][0] + b0, acc[nt][1] + b1);
        if (gr1 < N_NODES)
            *(float2*)(O + (size_t)gr1 * 128 + col) = make_float2(acc[nt][2] + b0, acc[nt][3] + b1);
    }
}

// ---------------- launch ------------------------------------------------------
extern "C" void kernel_launch(void* const* d_in, const int* in_sizes, int n_in,
                              void* d_out, int out_size)
{
    (void)in_sizes; (void)n_in; (void)out_size;
    const float*    x    = (const float*)d_in[0];
    const int*      ei   = (const int*)d_in[1];
    const unsigned* mask = (const unsigned*)d_in[2];
    const float*    W1l  = (const float*)d_in[3];
    const float*    b1   = (const float*)d_in[4];
    const float*    W1r  = (const float*)d_in[5];
    const float*    Ws   = (const float*)d_in[6];
    const float*    bs   = (const float*)d_in[7];
    const float*    W2l  = (const float*)d_in[8];
    const float*    b2   = (const float*)d_in[9];
    const float*    W2r  = (const float*)d_in[10];
    const float*    Wo   = (const float*)d_in[11];
    const float*    bo   = (const float*)d_in[12];
    float*          out  = (float*)d_out;

    const int* src = ei;
    const int* dst = ei + N_EDGES;

    void *p_agg, *p_h, *p_h2;
    cudaGetSymbolAddress(&p_agg, g_agg);
    cudaGetSymbolAddress(&p_h,   g_h);
    cudaGetSymbolAddress(&p_h2,  g_h2);
    float* agg = (float*)p_agg;
    float* h   = (float*)p_h;
    float* h2  = (float*)p_h2;

    const int SMEM_SKIP   = (1024 + 2 * 2304 + 3 * 9216) * 4;  // 133120 B
    const int SMEM_NOSKIP = (1024 + 2 * 2304 + 2 * 9216) * 4;  //  96256 B
    const int SMEM_OUT    = (256 + 2304 + 4608) * 4;           //  28672 B
    cudaFuncSetAttribute(layer_mma<true>,  cudaFuncAttributeMaxDynamicSharedMemorySize, SMEM_SKIP);
    cudaFuncSetAttribute(layer_mma<false>, cudaFuncAttributeMaxDynamicSharedMemorySize, SMEM_NOSKIP);
    cudaFuncSetAttribute(out_mma,          cudaFuncAttributeMaxDynamicSharedMemorySize, SMEM_OUT);

    int nb_nodes = (N_NODES + 255) / 256;
    int nb_edges = (N_EDGES + 255) / 256;
    int nb_warps = (N_NODES * 32 + 255) / 256;
    int nb_m     = (N_NODES + 63) / 64;     // 782
    int nb_scan1 = (N_NODES + 511) / 512;   // 98

    // CSR build
    zero_kernel<<<nb_nodes, 256>>>();
    count_kernel<<<nb_edges, 256>>>(dst, mask);
    scan1_kernel<<<nb_scan1, 512>>>();
    scan2_kernel<<<1, 128>>>();
    scan3_kernel<<<nb_nodes, 256>>>();
    scatter_kernel<<<nb_edges, 256>>>(src, dst, mask);

    // Layer 1: mean over ALL edges, fused tf32-MMA GEMM + norm + skip + tanh
    agg1_kernel<<<nb_warps, 256>>>(x);
    layer_mma<true><<<nb_m, 256, SMEM_SKIP>>>(agg, x, 128, W1l, W1r, b1, Ws, bs, h);

    // Layer 2: mean over masked edges, fused tf32-MMA GEMM + norm + tanh
    agg2_kernel<<<nb_warps, 256>>>();
    layer_mma<false><<<nb_m, 256, SMEM_NOSKIP>>>(agg, h, 256, W2l, W2r, b2, nullptr, nullptr, h2);

    // Output projection
    out_mma<<<nb_m, 256, SMEM_OUT>>>(h2, Wo, bo, out);
}

// round 4
// speedup vs baseline: 5.1169x; 1.6130x over previous
#include <cuda_runtime.h>
#include <cuda_fp16.h>
#include <math.h>
#include <stdint.h>

#define N_NODES 50000
#define N_EDGES 600000

// ---------------- scratch (device globals) -----------------------------------
__device__ int      g_deg[N_NODES];
__device__ int      g_cnt2[N_NODES];
__device__ int      g_off[N_NODES + 1];
__device__ int      g_pos[N_NODES];
__device__ int      g_bsum[128];
__device__ int      g_boff[128];
__device__ unsigned g_csr[N_EDGES];                   // src | (mask<<31)
__device__ __half   g_x16 [(size_t)N_NODES * 128];
__device__ __half   g_agg16[(size_t)N_NODES * 256];   // stride 128 for layer1, 256 for layer2
__device__ __half   g_h16 [(size_t)N_NODES * 256];
__device__ __half   g_h2  [(size_t)N_NODES * 256];
__device__ __half   g_y2  [(size_t)N_NODES * 256];
__device__ __half   g_w16 [262144];

#define OFF_W1L 0
#define OFF_W1R 32768
#define OFF_WS  65536
#define OFF_W2L 98304
#define OFF_W2R 163840
#define OFF_WO  229376

// ---------------- prep: zero counters + convert x & weights to fp16 ----------
__global__ void prep_kernel(const float* __restrict__ x,
                            const float* __restrict__ W1l, const float* __restrict__ W1r,
                            const float* __restrict__ Ws,  const float* __restrict__ W2l,
                            const float* __restrict__ W2r, const float* __restrict__ Wo) {
    int tid = blockIdx.x * blockDim.x + threadIdx.x;
    int tot = gridDim.x * blockDim.x;
    for (int i = tid; i < N_NODES; i += tot) { g_deg[i] = 0; g_cnt2[i] = 0; }
    for (int i = tid; i < N_NODES * 128 / 4; i += tot) {
        float4 v = ((const float4*)x)[i];
        __half2* d = (__half2*)(g_x16 + (size_t)i * 4);
        d[0] = __floats2half2_rn(v.x, v.y);
        d[1] = __floats2half2_rn(v.z, v.w);
    }
    const float* srcs[6] = {W1l, W1r, Ws, W2l, W2r, Wo};
    const int    lens[6] = {32768, 32768, 32768, 65536, 65536, 32768};
    const int    offs[6] = {OFF_W1L, OFF_W1R, OFF_WS, OFF_W2L, OFF_W2R, OFF_WO};
#pragma unroll
    for (int s = 0; s < 6; s++) {
        const float4* sp = (const float4*)srcs[s];
        __half2* dp = (__half2*)(g_w16 + offs[s]);
        for (int i = tid; i < lens[s] / 4; i += tot) {
            float4 v = sp[i];
            dp[i * 2]     = __floats2half2_rn(v.x, v.y);
            dp[i * 2 + 1] = __floats2half2_rn(v.z, v.w);
        }
    }
}

// ---------------- CSR build --------------------------------------------------
__global__ void count_kernel(const int* __restrict__ dst, const unsigned* __restrict__ mask) {
    int e = blockIdx.x * blockDim.x + threadIdx.x;
    if (e >= N_EDGES) return;
    int d = dst[e];
    atomicAdd(&g_deg[d], 1);
    if (mask[e] != 0u) atomicAdd(&g_cnt2[d], 1);
}

__global__ void scan1_kernel() {
    __shared__ int sh[512];
    int b = blockIdx.x, tid = threadIdx.x;
    int i = b * 512 + tid;
    int v = (i < N_NODES) ? g_deg[i] : 0;
    sh[tid] = v;
    __syncthreads();
    for (int o = 1; o < 512; o <<= 1) {
        int t = (tid >= o) ? sh[tid - o] : 0;
        __syncthreads();
        sh[tid] += t;
        __syncthreads();
    }
    if (i < N_NODES) g_off[i] = sh[tid] - v;
    if (tid == 511) g_bsum[b] = sh[511];
}

__global__ void scan2_kernel() {
    __shared__ int sh[128];
    int tid = threadIdx.x;
    const int nb = (N_NODES + 511) / 512;
    int v = (tid < nb) ? g_bsum[tid] : 0;
    sh[tid] = v;
    __syncthreads();
    for (int o = 1; o < 128; o <<= 1) {
        int t = (tid >= o) ? sh[tid - o] : 0;
        __syncthreads();
        sh[tid] += t;
        __syncthreads();
    }
    if (tid < nb) g_boff[tid] = sh[tid] - v;
}

__global__ void scan3_kernel() {
    int i = blockIdx.x * blockDim.x + threadIdx.x;
    if (i < N_NODES) {
        int o = g_off[i] + g_boff[i >> 9];
        g_off[i] = o;
        g_pos[i] = o;
        if (i == 0) g_off[N_NODES] = N_EDGES;
    }
}

__global__ void scatter_kernel(const int* __restrict__ src, const int* __restrict__ dst,
                               const unsigned* __restrict__ mask) {
    int e = blockIdx.x * blockDim.x + threadIdx.x;
    if (e >= N_EDGES) return;
    int d = dst[e];
    int slot = atomicAdd(&g_pos[d], 1);
    unsigned ent = (unsigned)src[e];
    if (mask[e] != 0u) ent |= 0x80000000u;
    g_csr[slot] = ent;
}

// ---------------- aggregation (warp per node, fp16 gather) -------------------
__global__ void agg1_kernel() {
    int w    = (blockIdx.x * blockDim.x + threadIdx.x) >> 5;
    int lane = threadIdx.x & 31;
    if (w >= N_NODES) return;
    int beg = g_off[w], end = g_off[w + 1];
    float4 acc = make_float4(0.f, 0.f, 0.f, 0.f);
    for (int p = beg; p < end; ++p) {
        unsigned ent = g_csr[p];
        int s = (int)(ent & 0x7fffffffu);
        uint2 t = *(const uint2*)(g_x16 + (size_t)s * 128 + lane * 4);
        float2 f0 = __half22float2(*(__half2*)&t.x);
        float2 f1 = __half22float2(*(__half2*)&t.y);
        acc.x += f0.x; acc.y += f0.y; acc.z += f1.x; acc.w += f1.y;
    }
    int deg = end - beg;
    float inv = 1.0f / (float)(deg > 1 ? deg : 1);
    __half2 o0 = __floats2half2_rn(acc.x * inv, acc.y * inv);
    __half2 o1 = __floats2half2_rn(acc.z * inv, acc.w * inv);
    uint2 o; o.x = *(unsigned*)&o0; o.y = *(unsigned*)&o1;
    *(uint2*)(g_agg16 + (size_t)w * 128 + lane * 4) = o;
}

__global__ void agg2_kernel() {
    int w    = (blockIdx.x * blockDim.x + threadIdx.x) >> 5;
    int lane = threadIdx.x & 31;
    if (w >= N_NODES) return;
    int beg = g_off[w], end = g_off[w + 1];
    float a[8];
#pragma unroll
    for (int j = 0; j < 8; j++) a[j] = 0.f;
    for (int p = beg; p < end; ++p) {
        unsigned ent = g_csr[p];
        if (ent & 0x80000000u) {
            int s = (int)(ent & 0x7fffffffu);
            uint4 t = *(const uint4*)(g_h16 + (size_t)s * 256 + lane * 8);
            float2 f0 = __half22float2(*(__half2*)&t.x);
            float2 f1 = __half22float2(*(__half2*)&t.y);
            float2 f2 = __half22float2(*(__half2*)&t.z);
            float2 f3 = __half22float2(*(__half2*)&t.w);
            a[0] += f0.x; a[1] += f0.y; a[2] += f1.x; a[3] += f1.y;
            a[4] += f2.x; a[5] += f2.y; a[6] += f3.x; a[7] += f3.y;
        }
    }
    int c = g_cnt2[w];
    float inv = 1.0f / (float)(c > 1 ? c : 1);
    __half2 o0 = __floats2half2_rn(a[0] * inv, a[1] * inv);
    __half2 o1 = __floats2half2_rn(a[2] * inv, a[3] * inv);
    __half2 o2 = __floats2half2_rn(a[4] * inv, a[5] * inv);
    __half2 o3 = __floats2half2_rn(a[6] * inv, a[7] * inv);
    uint4 o;
    o.x = *(unsigned*)&o0; o.y = *(unsigned*)&o1;
    o.z = *(unsigned*)&o2; o.w = *(unsigned*)&o3;
    *(uint4*)(g_agg16 + (size_t)w * 256 + lane * 8) = o;
}

// ---------------- mma.sync fp16 helpers ---------------------------------------
__device__ __forceinline__ void mma16(float* d, const unsigned* a, const unsigned* b) {
    asm volatile(
        "mma.sync.aligned.m16n8k16.row.col.f32.f16.f16.f32 "
        "{%0,%1,%2,%3}, {%4,%5,%6,%7}, {%8,%9}, {%0,%1,%2,%3};"
        : "+f"(d[0]), "+f"(d[1]), "+f"(d[2]), "+f"(d[3])
        : "r"(a[0]), "r"(a[1]), "r"(a[2]), "r"(a[3]), "r"(b[0]), "r"(b[1]));
}

// Load ROWS x 64-half tile into smem (row stride 72 halves). 256 threads.
template <int ROWS>
__device__ __forceinline__ void load16(__half* s, const __half* __restrict__ g,
                                       int ld, int k0, int row0, int maxrow) {
    int tid = threadIdx.x;
#pragma unroll
    for (int it = 0; it < ROWS / 32; ++it) {
        int idx = it * 256 + tid;
        int r = idx >> 3, sg = idx & 7;
        uint4 v = make_uint4(0, 0, 0, 0);
        if (row0 + r < maxrow) v = *(const uint4*)(g + (size_t)(row0 + r) * ld + k0 + sg * 8);
        *(uint4*)(s + r * 72 + sg * 8) = v;
    }
}

// ---------------- fused SAGE layer (acc = A1@Wl^T + A2@Wr^T) ------------------
// 8 warps: warp(wm 0..1, wn 0..3) = rows 32*wm..+31, cols 64*wn..+63 of 64x256 tile.
// epilogue: +bias, row L2-norm, (+Y2), tanh -> H (fp16)
template <bool ADD_Y2>
__global__ __launch_bounds__(256, 2) void layer_fused(
    const __half* __restrict__ A1, int ldA1, const __half* __restrict__ A2, int ldA2, int K,
    const __half* __restrict__ Wl, const __half* __restrict__ Wr,
    const float* __restrict__ bias,
    const __half* __restrict__ Y2, __half* __restrict__ H)
{
    extern __shared__ char smraw[];
    float*  sB   = (float*)smraw;                 // 256
    float*  sred = sB + 256;                      // 256
    __half* sA1  = (__half*)(sred + 256);         // 64*72
    __half* sA2  = sA1 + 64 * 72;
    __half* sWl  = sA2 + 64 * 72;                 // 256*72
    __half* sWr  = sWl + 256 * 72;

    int tid = threadIdx.x, lane = tid & 31, w = tid >> 5;
    int wm = w >> 2, wn = w & 3;
    int g = lane >> 2, t = lane & 3;
    int row0 = blockIdx.x * 64;

    if (tid < 256) sB[tid] = bias[tid];

    float acc[2][8][4];
#pragma unroll
    for (int mt = 0; mt < 2; mt++)
#pragma unroll
        for (int nt = 0; nt < 8; nt++)
#pragma unroll
            for (int j = 0; j < 4; j++) acc[mt][nt][j] = 0.f;

    for (int c = 0; c < (K >> 6); c++) {
        int k0 = c << 6;
        load16<64>(sA1, A1, ldA1, k0, row0, N_NODES);
        load16<64>(sA2, A2, ldA2, k0, row0, N_NODES);
        load16<256>(sWl, Wl, K, k0, 0, 256);
        load16<256>(sWr, Wr, K, k0, 0, 256);
        __syncthreads();
        const unsigned* uA1 = (const unsigned*)sA1;
        const unsigned* uA2 = (const unsigned*)sA2;
        const unsigned* uWl = (const unsigned*)sWl;
        const unsigned* uWr = (const unsigned*)sWr;
#pragma unroll
        for (int ks = 0; ks < 4; ks++) {
            int wb = ks * 8 + t;
            unsigned a1f[2][4], a2f[2][4];
#pragma unroll
            for (int mt = 0; mt < 2; mt++) {
                int r = 32 * wm + 16 * mt + g;
                a1f[mt][0] = uA1[r * 36 + wb];
                a1f[mt][1] = uA1[(r + 8) * 36 + wb];
                a1f[mt][2] = uA1[r * 36 + wb + 4];
                a1f[mt][3] = uA1[(r + 8) * 36 + wb + 4];
                a2f[mt][0] = uA2[r * 36 + wb];
                a2f[mt][1] = uA2[(r + 8) * 36 + wb];
                a2f[mt][2] = uA2[r * 36 + wb + 4];
                a2f[mt][3] = uA2[(r + 8) * 36 + wb + 4];
            }
#pragma unroll
            for (int nt = 0; nt < 8; nt++) {
                int n = 64 * wn + 8 * nt + g;
                unsigned bl[2], br[2];
                bl[0] = uWl[n * 36 + wb]; bl[1] = uWl[n * 36 + wb + 4];
                br[0] = uWr[n * 36 + wb]; br[1] = uWr[n * 36 + wb + 4];
                mma16(acc[0][nt], a1f[0], bl);
                mma16(acc[0][nt], a2f[0], br);
                mma16(acc[1][nt], a1f[1], bl);
                mma16(acc[1][nt], a2f[1], br);
            }
        }
        __syncthreads();
    }

    // +bias, per-row sum of squares
#pragma unroll
    for (int mt = 0; mt < 2; mt++) {
        float s0 = 0.f, s1 = 0.f;
#pragma unroll
        for (int nt = 0; nt < 8; nt++) {
            int col = 64 * wn + 8 * nt + 2 * t;
            acc[mt][nt][0] += sB[col];
            acc[mt][nt][1] += sB[col + 1];
            acc[mt][nt][2] += sB[col];
            acc[mt][nt][3] += sB[col + 1];
            s0 += acc[mt][nt][0] * acc[mt][nt][0] + acc[mt][nt][1] * acc[mt][nt][1];
            s1 += acc[mt][nt][2] * acc[mt][nt][2] + acc[mt][nt][3] * acc[mt][nt][3];
        }
        s0 += __shfl_xor_sync(0xffffffffu, s0, 1);
        s0 += __shfl_xor_sync(0xffffffffu, s0, 2);
        s1 += __shfl_xor_sync(0xffffffffu, s1, 1);
        s1 += __shfl_xor_sync(0xffffffffu, s1, 2);
        if (t == 0) {
            int r = 32 * wm + 16 * mt + g;
            sred[r * 4 + wn] = s0;
            sred[(r + 8) * 4 + wn] = s1;
        }
    }
    __syncthreads();

#pragma unroll
    for (int mt = 0; mt < 2; mt++) {
        int r0 = 32 * wm + 16 * mt + g, r1 = r0 + 8;
        float n0 = sred[r0 * 4] + sred[r0 * 4 + 1] + sred[r0 * 4 + 2] + sred[r0 * 4 + 3];
        float n1 = sred[r1 * 4] + sred[r1 * 4 + 1] + sred[r1 * 4 + 2] + sred[r1 * 4 + 3];
        float inv0 = 1.f / fmaxf(sqrtf(n0), 1e-12f);
        float inv1 = 1.f / fmaxf(sqrtf(n1), 1e-12f);
        int gr0 = row0 + r0, gr1 = row0 + r1;
#pragma unroll
        for (int nt = 0; nt < 8; nt++) {
            int col = 64 * wn + 8 * nt + 2 * t;
            if (gr0 < N_NODES) {
                float v0 = acc[mt][nt][0] * inv0, v1 = acc[mt][nt][1] * inv0;
                if (ADD_Y2) {
                    __half2 y = *(const __half2*)(Y2 + (size_t)gr0 * 256 + col);
                    float2 f = __half22float2(y);
                    v0 += f.x; v1 += f.y;
                }
                __half2 o = __floats2half2_rn(tanhf(v0), tanhf(v1));
                *(__half2*)(H + (size_t)gr0 * 256 + col) = o;
            }
            if (gr1 < N_NODES) {
                float v2 = acc[mt][nt][2] * inv1, v3 = acc[mt][nt][3] * inv1;
                if (ADD_Y2) {
                    __half2 y = *(const __half2*)(Y2 + (size_t)gr1 * 256 + col);
                    float2 f = __half22float2(y);
                    v2 += f.x; v3 += f.y;
                }
                __half2 o = __floats2half2_rn(tanhf(v2), tanhf(v3));
                *(__half2*)(H + (size_t)gr1 * 256 + col) = o;
            }
        }
    }
}

// ---------------- skip GEMM: Y = A@W^T + bias (K=128, N=256) ------------------
__global__ __launch_bounds__(256, 2) void skip_mma(
    const __half* __restrict__ A, const __half* __restrict__ W,
    const float* __restrict__ bias, __half* __restrict__ Y)
{
    extern __shared__ char smraw[];
    float*  sB = (float*)smraw;               // 256
    __half* sA = (__half*)(sB + 256);         // 64*72
    __half* sW = sA + 64 * 72;                // 256*72

    int tid = threadIdx.x, lane = tid & 31, w = tid >> 5;
    int wm = w >> 2, wn = w & 3;
    int g = lane >> 2, t = lane & 3;
    int row0 = blockIdx.x * 64;
    const int K = 128;

    if (tid < 256) sB[tid] = bias[tid];

    float acc[2][8][4];
#pragma unroll
    for (int mt = 0; mt < 2; mt++)
#pragma unroll
        for (int nt = 0; nt < 8; nt++)
#pragma unroll
            for (int j = 0; j < 4; j++) acc[mt][nt][j] = 0.f;

    for (int c = 0; c < 2; c++) {
        int k0 = c << 6;
        load16<64>(sA, A, K, k0, row0, N_NODES);
        load16<256>(sW, W, K, k0, 0, 256);
        __syncthreads();
        const unsigned* uA = (const unsigned*)sA;
        const unsigned* uW = (const unsigned*)sW;
#pragma unroll
        for (int ks = 0; ks < 4; ks++) {
            int wb = ks * 8 + t;
            unsigned af[2][4];
#pragma unroll
            for (int mt = 0; mt < 2; mt++) {
                int r = 32 * wm + 16 * mt + g;
                af[mt][0] = uA[r * 36 + wb];
                af[mt][1] = uA[(r + 8) * 36 + wb];
                af[mt][2] = uA[r * 36 + wb + 4];
                af[mt][3] = uA[(r + 8) * 36 + wb + 4];
            }
#pragma unroll
            for (int nt = 0; nt < 8; nt++) {
                int n = 64 * wn + 8 * nt + g;
                unsigned bf[2];
                bf[0] = uW[n * 36 + wb]; bf[1] = uW[n * 36 + wb + 4];
                mma16(acc[0][nt], af[0], bf);
                mma16(acc[1][nt], af[1], bf);
            }
        }
        __syncthreads();
    }

#pragma unroll
    for (int mt = 0; mt < 2; mt++) {
        int gr0 = row0 + 32 * wm + 16 * mt + g, gr1 = gr0 + 8;
#pragma unroll
        for (int nt = 0; nt < 8; nt++) {
            int col = 64 * wn + 8 * nt + 2 * t;
            float b0 = sB[col], b1 = sB[col + 1];
            if (gr0 < N_NODES) {
                __half2 o = __floats2half2_rn(acc[mt][nt][0] + b0, acc[mt][nt][1] + b1);
                *(__half2*)(Y + (size_t)gr0 * 256 + col) = o;
            }
            if (gr1 < N_NODES) {
                __half2 o = __floats2half2_rn(acc[mt][nt][2] + b0, acc[mt][nt][3] + b1);
                *(__half2*)(Y + (size_t)gr1 * 256 + col) = o;
            }
        }
    }
}

// ---------------- output GEMM: O = A@Wo^T + bo (K=256, N=128, fp32 out) -------
__global__ __launch_bounds__(256, 2) void out_mma(
    const __half* __restrict__ A, const __half* __restrict__ W,
    const float* __restrict__ bias, float* __restrict__ O)
{
    extern __shared__ char smraw[];
    float*  sB = (float*)smraw;               // 128
    __half* sA = (__half*)(sB + 128);         // 64*72
    __half* sW = sA + 64 * 72;                // 128*72

    int tid = threadIdx.x, lane = tid & 31, w = tid >> 5;
    int wm = w >> 1, wn = w & 1;
    int g = lane >> 2, t = lane & 3;
    int row0 = blockIdx.x * 64;
    const int K = 256;

    if (tid < 128) sB[tid] = bias[tid];

    float acc[8][4];
#pragma unroll
    for (int nt = 0; nt < 8; nt++)
#pragma unroll
        for (int j = 0; j < 4; j++) acc[nt][j] = 0.f;

    for (int c = 0; c < 4; c++) {
        int k0 = c << 6;
        load16<64>(sA, A, K, k0, row0, N_NODES);
        load16<128>(sW, W, K, k0, 0, 128);
        __syncthreads();
        const unsigned* uA = (const unsigned*)sA;
        const unsigned* uW = (const unsigned*)sW;
#pragma unroll
        for (int ks = 0; ks < 4; ks++) {
            int wb = ks * 8 + t;
            unsigned af[4];
            int r = 16 * wm + g;
            af[0] = uA[r * 36 + wb];
            af[1] = uA[(r + 8) * 36 + wb];
            af[2] = uA[r * 36 + wb + 4];
            af[3] = uA[(r + 8) * 36 + wb + 4];
#pragma unroll
            for (int nt = 0; nt < 8; nt++) {
                int n = 64 * wn + 8 * nt + g;
                unsigned bf[2];
                bf[0] = uW[n * 36 + wb]; bf[1] = uW[n * 36 + wb + 4];
                mma16(acc[nt], af, bf);
            }
        }
        __syncthreads();
    }

    int gr0 = row0 + 16 * wm + g, gr1 = gr0 + 8;
#pragma unroll
    for (int nt = 0; nt < 8; nt++) {
        int col = 64 * wn + 8 * nt + 2 * t;
        float b0 = sB[col], b1 = sB[col + 1];
        if (gr0 < N_NODES)
            *(float2*)(O + (size_t)gr0 * 128 + col) = make_float2(acc[nt][0] + b0, acc[nt][1] + b1);
        if (gr1 < N_NODES)
            *(float2*)(O + (size_t)gr1 * 128 + col) = make_float2(acc[nt][2] + b0, acc[nt][3] + b1);
    }
}

// ---------------- launch ------------------------------------------------------
extern "C" void kernel_launch(void* const* d_in, const int* in_sizes, int n_in,
                              void* d_out, int out_size)
{
    (void)in_sizes; (void)n_in; (void)out_size;
    const float*    x    = (const float*)d_in[0];
    const int*      ei   = (const int*)d_in[1];
    const unsigned* mask = (const unsigned*)d_in[2];
    const float*    W1l  = (const float*)d_in[3];
    const float*    b1   = (const float*)d_in[4];
    const float*    W1r  = (const float*)d_in[5];
    const float*    Ws   = (const float*)d_in[6];
    const float*    bs   = (const float*)d_in[7];
    const float*    W2l  = (const float*)d_in[8];
    const float*    b2   = (const float*)d_in[9];
    const float*    W2r  = (const float*)d_in[10];
    const float*    Wo   = (const float*)d_in[11];
    const float*    bo   = (const float*)d_in[12];
    float*          out  = (float*)d_out;

    const int* src = ei;
    const int* dst = ei + N_EDGES;

    void *p_x16, *p_agg, *p_h, *p_h2, *p_y2, *p_w;
    cudaGetSymbolAddress(&p_x16, g_x16);
    cudaGetSymbolAddress(&p_agg, g_agg16);
    cudaGetSymbolAddress(&p_h,   g_h16);
    cudaGetSymbolAddress(&p_h2,  g_h2);
    cudaGetSymbolAddress(&p_y2,  g_y2);
    cudaGetSymbolAddress(&p_w,   g_w16);
    __half* x16 = (__half*)p_x16;
    __half* agg = (__half*)p_agg;
    __half* h   = (__half*)p_h;
    __half* h2  = (__half*)p_h2;
    __half* y2  = (__half*)p_y2;
    __half* w16 = (__half*)p_w;

    const int SM_LAYER = 512 * 4 + (2 * 64 * 72 + 2 * 256 * 72) * 2;   // 94208
    const int SM_SKIP  = 256 * 4 + (64 * 72 + 256 * 72) * 2;           // 47104
    const int SM_OUT   = 128 * 4 + (64 * 72 + 128 * 72) * 2;           // 28160
    cudaFuncSetAttribute(layer_fused<true>,  cudaFuncAttributeMaxDynamicSharedMemorySize, SM_LAYER);
    cudaFuncSetAttribute(layer_fused<false>, cudaFuncAttributeMaxDynamicSharedMemorySize, SM_LAYER);
    cudaFuncSetAttribute(skip_mma,           cudaFuncAttributeMaxDynamicSharedMemorySize, SM_SKIP);
    cudaFuncSetAttribute(out_mma,            cudaFuncAttributeMaxDynamicSharedMemorySize, SM_OUT);

    int nb_nodes = (N_NODES + 255) / 256;
    int nb_edges = (N_EDGES + 255) / 256;
    int nb_warps = (N_NODES * 32 + 255) / 256;
    int nb_m     = (N_NODES + 63) / 64;     // 782
    int nb_scan1 = (N_NODES + 511) / 512;   // 98

    // prep (zero counters + fp16 conversions), CSR build
    prep_kernel<<<1024, 256>>>(x, W1l, W1r, Ws, W2l, W2r, Wo);
    count_kernel<<<nb_edges, 256>>>(dst, mask);
    scan1_kernel<<<nb_scan1, 512>>>();
    scan2_kernel<<<1, 128>>>();
    scan3_kernel<<<nb_nodes, 256>>>();
    scatter_kernel<<<nb_edges, 256>>>(src, dst, mask);

    // skip GEMM (independent of graph): y2 = x@Ws^T + bs
    skip_mma<<<nb_m, 256, SM_SKIP>>>(x16, w16 + OFF_WS, bs, y2);

    // Layer 1
    agg1_kernel<<<nb_warps, 256>>>();
    layer_fused<true><<<nb_m, 256, SM_LAYER>>>(
        agg, 128, x16, 128, 128, w16 + OFF_W1L, w16 + OFF_W1R, b1, y2, h);

    // Layer 2
    agg2_kernel<<<nb_warps, 256>>>();
    layer_fused<false><<<nb_m, 256, SM_LAYER>>>(
        agg, 256, h, 256, 256, w16 + OFF_W2L, w16 + OFF_W2R, b2, nullptr, h2);

    // Output projection
    out_mma<<<nb_m, 256, SM_OUT>>>(h2, w16 + OFF_WO, bo, out);
}